// round 4
// baseline (speedup 1.0000x reference)
#include <cuda_runtime.h>
#include <cstdint>

// ---- problem dims ----
#define T_TOK 2048   // B*S tokens
#define HID   2048   // hidden size (K of GEMM1, N of GEMM2)
#define EXP   8      // experts
#define N1    4096   // 2*D (interleaved gate/up), N of GEMM1
#define DDIM  2048   // expert dim
#define K2    16384  // E*D, K of GEMM2

// ---- tiling ----
constexpr int BM = 128, BN = 128, BK = 16;
constexpr int ASTR = 20;    // SMEM word stride for A tile rows (conflict-free)
constexpr int BSTR = 136;   // SMEM word stride for B tile rows (conflict-free)
constexpr int NTHR = 256;

// scratch: rw-scaled GLU activations, [T_TOK][K2] fp32 (128 MB)
__device__ __align__(128) float g_fw[(size_t)T_TOK * K2];

__device__ __forceinline__ uint32_t f2tf(float f) {
    uint32_t u;
    asm("cvt.rna.tf32.f32 %0, %1;" : "=r"(u) : "f"(f));
    return u;
}

__device__ __forceinline__ void mma8(float* c, const uint32_t* a, const uint32_t* b) {
    asm volatile(
        "mma.sync.aligned.m16n8k8.row.col.f32.tf32.tf32.f32 "
        "{%0,%1,%2,%3}, {%4,%5,%6,%7}, {%8,%9}, {%0,%1,%2,%3};"
        : "+f"(c[0]), "+f"(c[1]), "+f"(c[2]), "+f"(c[3])
        : "r"(a[0]), "r"(a[1]), "r"(a[2]), "r"(a[3]), "r"(b[0]), "r"(b[1]));
}

// ============================================================================
// GEMM1: gate_up = x[T,H] @ W1[e][H,2D]  -> GLU epilogue -> g_fw (rw-scaled)
// ============================================================================
__global__ __launch_bounds__(NTHR) void k_gemm1(
    const float* __restrict__ x, const float* __restrict__ w1,
    const float* __restrict__ b1, const float* __restrict__ rw)
{
    __shared__ uint32_t sA[2][BM * ASTR];
    __shared__ uint32_t sB[2][BK * BSTR];

    const int m0 = blockIdx.x * BM;
    const int n0 = blockIdx.y * BN;
    const int e  = blockIdx.z;

    const float* __restrict__ pA = x;                               // lda = HID
    const float* __restrict__ pB = w1 + (size_t)e * HID * N1;       // ldb = N1

    const int tid  = threadIdx.x;
    const int lane = tid & 31;
    const int warp = tid >> 5;
    const int wm = (warp & 3) * 32;   // warp row offset in tile
    const int wn = (warp >> 2) * 64;  // warp col offset in tile

    float4 ra[2], rb[2];

    // --- loaders (register staging) ---
    auto ldgA = [&](int kt) {
        int k0 = kt * BK;
        #pragma unroll
        for (int i = 0; i < 2; i++) {
            int lin = tid + i * NTHR;          // 0..511
            int r = lin >> 2, c = (lin & 3) * 4;
            ra[i] = *(const float4*)(pA + (size_t)(m0 + r) * HID + k0 + c);
        }
    };
    auto ldgB = [&](int kt) {
        int k0 = kt * BK;
        #pragma unroll
        for (int i = 0; i < 2; i++) {
            int lin = tid + i * NTHR;
            int r = lin >> 5, c = (lin & 31) * 4;
            rb[i] = *(const float4*)(pB + (size_t)(k0 + r) * N1 + n0 + c);
        }
    };
    auto stsAB = [&](int p) {
        #pragma unroll
        for (int i = 0; i < 2; i++) {
            int lin = tid + i * NTHR;
            int r = lin >> 2, c = (lin & 3) * 4;
            uint4 v = { f2tf(ra[i].x), f2tf(ra[i].y), f2tf(ra[i].z), f2tf(ra[i].w) };
            *(uint4*)&sA[p][r * ASTR + c] = v;
        }
        #pragma unroll
        for (int i = 0; i < 2; i++) {
            int lin = tid + i * NTHR;
            int r = lin >> 5, c = (lin & 31) * 4;
            uint4 v = { f2tf(rb[i].x), f2tf(rb[i].y), f2tf(rb[i].z), f2tf(rb[i].w) };
            *(uint4*)&sB[p][r * BSTR + c] = v;
        }
    };

    float acc[2][8][4];
    #pragma unroll
    for (int a = 0; a < 2; a++)
        #pragma unroll
        for (int b = 0; b < 8; b++)
            #pragma unroll
            for (int q = 0; q < 4; q++) acc[a][b][q] = 0.f;

    const int NK = HID / BK;  // 128
    ldgA(0); ldgB(0);
    stsAB(0);
    __syncthreads();

    int p = 0;
    for (int kt = 0; kt < NK; ++kt) {
        if (kt + 1 < NK) { ldgA(kt + 1); ldgB(kt + 1); }
        #pragma unroll
        for (int kk = 0; kk < 2; kk++) {
            const int kb = kk * 8;
            uint32_t af[2][4], bf[8][2];
            #pragma unroll
            for (int mt = 0; mt < 2; mt++) {
                int r = wm + mt * 16 + (lane >> 2);
                int c = kb + (lane & 3);
                af[mt][0] = sA[p][r * ASTR + c];
                af[mt][1] = sA[p][(r + 8) * ASTR + c];
                af[mt][2] = sA[p][r * ASTR + c + 4];
                af[mt][3] = sA[p][(r + 8) * ASTR + c + 4];
            }
            #pragma unroll
            for (int nt = 0; nt < 8; nt++) {
                int n = wn + nt * 8 + (lane >> 2);
                int k = kb + (lane & 3);
                bf[nt][0] = sB[p][k * BSTR + n];
                bf[nt][1] = sB[p][(k + 4) * BSTR + n];
            }
            #pragma unroll
            for (int mt = 0; mt < 2; mt++)
                #pragma unroll
                for (int nt = 0; nt < 8; nt++)
                    mma8(acc[mt][nt], af[mt], bf[nt]);
        }
        if (kt + 1 < NK) stsAB(1 - p);
        __syncthreads();
        p ^= 1;
    }

    // --- GLU epilogue: clamp, sigmoid, rw-scale, write g_fw ---
    #pragma unroll
    for (int mt = 0; mt < 2; mt++) {
        int r0 = m0 + wm + mt * 16 + (lane >> 2);
        int r1 = r0 + 8;
        float rw0 = rw[r0 * EXP + e];
        float rw1 = rw[r1 * EXP + e];
        #pragma unroll
        for (int nt = 0; nt < 8; nt++) {
            int cn = n0 + wn + nt * 8 + (lane & 3) * 2;  // even column (gate)
            int d  = cn >> 1;
            float bg = b1[e * N1 + cn];
            float bu = b1[e * N1 + cn + 1];
            // row r0
            {
                float g = fminf(acc[mt][nt][0] + bg, 7.f);
                float u = fminf(fmaxf(acc[mt][nt][1] + bu, -7.f), 7.f);
                float glu = g / (1.f + __expf(-1.702f * g));
                g_fw[(size_t)r0 * K2 + e * DDIM + d] = (u + 1.f) * glu * rw0;
            }
            // row r1
            {
                float g = fminf(acc[mt][nt][2] + bg, 7.f);
                float u = fminf(fmaxf(acc[mt][nt][3] + bu, -7.f), 7.f);
                float glu = g / (1.f + __expf(-1.702f * g));
                g_fw[(size_t)r1 * K2 + e * DDIM + d] = (u + 1.f) * glu * rw1;
            }
        }
    }
}

// ============================================================================
// GEMM2: out[T,H] = g_fw[T,K2] @ down_w_flat[K2,H] + sum_e rw[t,e]*down_b[e,h]
// (down_w [E,D,H] is contiguous as [K2,H] with k = e*D + d)
// ============================================================================
__global__ __launch_bounds__(NTHR) void k_gemm2(
    const float* __restrict__ w2, const float* __restrict__ b2,
    const float* __restrict__ rw, float* __restrict__ out)
{
    __shared__ uint32_t sA[2][BM * ASTR];
    __shared__ uint32_t sB[2][BK * BSTR];

    const int m0 = blockIdx.x * BM;
    const int n0 = blockIdx.y * BN;

    const int tid  = threadIdx.x;
    const int lane = tid & 31;
    const int warp = tid >> 5;
    const int wm = (warp & 3) * 32;
    const int wn = (warp >> 2) * 64;

    float4 ra[2], rb[2];

    auto ldgA = [&](int kt) {
        int k0 = kt * BK;
        #pragma unroll
        for (int i = 0; i < 2; i++) {
            int lin = tid + i * NTHR;
            int r = lin >> 2, c = (lin & 3) * 4;
            ra[i] = *(const float4*)(g_fw + (size_t)(m0 + r) * K2 + k0 + c);
        }
    };
    auto ldgB = [&](int kt) {
        int k0 = kt * BK;
        #pragma unroll
        for (int i = 0; i < 2; i++) {
            int lin = tid + i * NTHR;
            int r = lin >> 5, c = (lin & 31) * 4;
            rb[i] = *(const float4*)(w2 + (size_t)(k0 + r) * HID + n0 + c);
        }
    };
    auto stsAB = [&](int p) {
        #pragma unroll
        for (int i = 0; i < 2; i++) {
            int lin = tid + i * NTHR;
            int r = lin >> 2, c = (lin & 3) * 4;
            uint4 v = { f2tf(ra[i].x), f2tf(ra[i].y), f2tf(ra[i].z), f2tf(ra[i].w) };
            *(uint4*)&sA[p][r * ASTR + c] = v;
        }
        #pragma unroll
        for (int i = 0; i < 2; i++) {
            int lin = tid + i * NTHR;
            int r = lin >> 5, c = (lin & 31) * 4;
            uint4 v = { f2tf(rb[i].x), f2tf(rb[i].y), f2tf(rb[i].z), f2tf(rb[i].w) };
            *(uint4*)&sB[p][r * BSTR + c] = v;
        }
    };

    float acc[2][8][4];
    #pragma unroll
    for (int a = 0; a < 2; a++)
        #pragma unroll
        for (int b = 0; b < 8; b++)
            #pragma unroll
            for (int q = 0; q < 4; q++) acc[a][b][q] = 0.f;

    const int NK = K2 / BK;  // 1024
    ldgA(0); ldgB(0);
    stsAB(0);
    __syncthreads();

    int p = 0;
    for (int kt = 0; kt < NK; ++kt) {
        if (kt + 1 < NK) { ldgA(kt + 1); ldgB(kt + 1); }
        #pragma unroll
        for (int kk = 0; kk < 2; kk++) {
            const int kb = kk * 8;
            uint32_t af[2][4], bf[8][2];
            #pragma unroll
            for (int mt = 0; mt < 2; mt++) {
                int r = wm + mt * 16 + (lane >> 2);
                int c = kb + (lane & 3);
                af[mt][0] = sA[p][r * ASTR + c];
                af[mt][1] = sA[p][(r + 8) * ASTR + c];
                af[mt][2] = sA[p][r * ASTR + c + 4];
                af[mt][3] = sA[p][(r + 8) * ASTR + c + 4];
            }
            #pragma unroll
            for (int nt = 0; nt < 8; nt++) {
                int n = wn + nt * 8 + (lane >> 2);
                int k = kb + (lane & 3);
                bf[nt][0] = sB[p][k * BSTR + n];
                bf[nt][1] = sB[p][(k + 4) * BSTR + n];
            }
            #pragma unroll
            for (int mt = 0; mt < 2; mt++)
                #pragma unroll
                for (int nt = 0; nt < 8; nt++)
                    mma8(acc[mt][nt], af[mt], bf[nt]);
        }
        if (kt + 1 < NK) stsAB(1 - p);
        __syncthreads();
        p ^= 1;
    }

    // --- epilogue: bias mix  sum_e rw[t,e] * down_b[e,h] ---
    __syncthreads();
    float* dbs = (float*)&sA[0][0];      // [EXP][BN]
    float* rws = (float*)&sA[0][EXP * BN]; // [BM][EXP]
    for (int i = tid; i < EXP * BN; i += NTHR)
        dbs[i] = b2[(i / BN) * HID + n0 + (i % BN)];
    for (int i = tid; i < BM * EXP; i += NTHR)
        rws[i] = rw[(size_t)(m0 + i / EXP) * EXP + (i % EXP)];
    __syncthreads();

    #pragma unroll
    for (int mt = 0; mt < 2; mt++) {
        int rl0 = wm + mt * 16 + (lane >> 2);
        int rl1 = rl0 + 8;
        int r0 = m0 + rl0;
        #pragma unroll
        for (int nt = 0; nt < 8; nt++) {
            int nl = wn + nt * 8 + (lane & 3) * 2;
            int gn = n0 + nl;
            float b00 = 0.f, b01 = 0.f, b10 = 0.f, b11 = 0.f;
            #pragma unroll
            for (int q = 0; q < EXP; q++) {
                float d0 = dbs[q * BN + nl], d1 = dbs[q * BN + nl + 1];
                b00 += rws[rl0 * EXP + q] * d0;
                b01 += rws[rl0 * EXP + q] * d1;
                b10 += rws[rl1 * EXP + q] * d0;
                b11 += rws[rl1 * EXP + q] * d1;
            }
            float2 v0 = { acc[mt][nt][0] + b00, acc[mt][nt][1] + b01 };
            float2 v1 = { acc[mt][nt][2] + b10, acc[mt][nt][3] + b11 };
            *(float2*)&out[(size_t)r0 * HID + gn] = v0;
            *(float2*)&out[(size_t)(r0 + 8) * HID + gn] = v1;
        }
    }
}

extern "C" void kernel_launch(void* const* d_in, const int* in_sizes, int n_in,
                              void* d_out, int out_size) {
    const float* x  = (const float*)d_in[0];  // hidden_states [4,512,2048]
    const float* rw = (const float*)d_in[1];  // routing_weights [2048,8]
    const float* w1 = (const float*)d_in[2];  // gate_up_w [8,2048,4096]
    const float* b1 = (const float*)d_in[3];  // gate_up_b [8,4096]
    const float* w2 = (const float*)d_in[4];  // down_w [8,2048,2048]
    const float* b2 = (const float*)d_in[5];  // down_b [8,2048]
    float* out = (float*)d_out;

    dim3 blk(NTHR);
    k_gemm1<<<dim3(T_TOK / BM, N1 / BN, EXP), blk>>>(x, w1, b1, rw);
    k_gemm2<<<dim3(T_TOK / BM, HID / BN), blk>>>(w2, b2, rw, out);
}

// round 6
// speedup vs baseline: 1.0243x; 1.0243x over previous
#include <cuda_runtime.h>
#include <cstdint>

// ---- problem dims ----
#define T_TOK 2048
#define HID   2048
#define EXP   8
#define N1    4096
#define K2    16384
#define K2P   16416   // K2 + 32: bias folded into K (cols 16384..16391 = rw / down_b)

// ---- tiling ----
constexpr int BM = 128, BN = 256, BK = 16;
constexpr int NTHR = 512;             // 16 warps: 4 (m) x 4 (n), warp tile 32x64
constexpr int NSTG = 4;
constexpr int ASTR = 20, BSTR = 20;   // words/row; conflict-free for ldmatrix
constexpr int ABYTES = BM * ASTR * 4;       // 10240
constexpr int BBYTES = BN * BSTR * 4;       // 20480
constexpr int STG = ABYTES + BBYTES;        // 30720
constexpr int SMEM_SZ = NSTG * STG;         // 122880

// ---- scratch (device globals; allocation forbidden) ----
__device__ __align__(1024) float g_xc [(size_t)T_TOK * HID];      // tf32-rounded x
__device__ __align__(1024) float g_w1t[(size_t)EXP * N1 * HID];   // [e][n][h]
__device__ __align__(1024) float g_w2t[(size_t)HID * K2P];        // [h][k] (+bias tail)
__device__ __align__(1024) float g_fw [(size_t)T_TOK * K2P];      // rw-scaled GLU (+rw tail)

// ===================== helpers =====================
__device__ __forceinline__ uint32_t smem_u32(const void* p) {
    uint32_t a;
    asm("{ .reg .u64 t; cvta.to.shared.u64 t, %1; cvt.u32.u64 %0, t; }" : "=r"(a) : "l"(p));
    return a;
}
__device__ __forceinline__ uint32_t f2tf(float f) {
    uint32_t u; asm("cvt.rna.tf32.f32 %0, %1;" : "=r"(u) : "f"(f)); return u;
}
__device__ __forceinline__ void mma8(float* c, const uint32_t* a, const uint32_t* b) {
    asm volatile(
        "mma.sync.aligned.m16n8k8.row.col.f32.tf32.tf32.f32 "
        "{%0,%1,%2,%3}, {%4,%5,%6,%7}, {%8,%9}, {%0,%1,%2,%3};"
        : "+f"(c[0]), "+f"(c[1]), "+f"(c[2]), "+f"(c[3])
        : "r"(a[0]), "r"(a[1]), "r"(a[2]), "r"(a[3]), "r"(b[0]), "r"(b[1]));
}
__device__ __forceinline__ void ldsm4(uint32_t* r, uint32_t addr) {
    asm volatile("ldmatrix.sync.aligned.m8n8.x4.shared.b16 {%0,%1,%2,%3}, [%4];"
                 : "=r"(r[0]), "=r"(r[1]), "=r"(r[2]), "=r"(r[3]) : "r"(addr));
}
__device__ __forceinline__ void cp16(uint32_t s, const void* g) {
    asm volatile("cp.async.cg.shared.global [%0], [%1], 16;" :: "r"(s), "l"(g) : "memory");
}
__device__ __forceinline__ void cp_commit() {
    asm volatile("cp.async.commit_group;" ::: "memory");
}
__device__ __forceinline__ void cp_wait2() {
    asm volatile("cp.async.wait_group 2;" ::: "memory");
}

// ===================== main GEMM loop (shared by both kernels) =====================
// pA: [>=BM rows] x lda (k-contiguous, tf32-rounded). pB: [>=BN rows] x lda.
// acc[mt][nt][4] per thread, warp tile 32(m) x 64(n).
__device__ __forceinline__ void gemm_main(
    const float* __restrict__ pA, const float* __restrict__ pB,
    size_t lda, int NK, uint32_t su, float acc[2][8][4])
{
    const int tid  = threadIdx.x;
    const int lane = tid & 31;
    const int w    = tid >> 5;
    const int wm   = (w & 3) * 32;
    const int wn   = (w >> 2) * 64;

    // -- cp.async addressing: A 512 float4 (1/thr), B 1024 float4 (2/thr) --
    const int ar = tid >> 2, aq = tid & 3;
    const float* asrc  = pA + (size_t)ar * lda + aq * 4;
    const float* bsrc0 = pB + (size_t)ar * lda + aq * 4;           // rows 0..127
    const float* bsrc1 = pB + (size_t)(ar + 128) * lda + aq * 4;   // rows 128..255
    const uint32_t adst  = su + (ar * ASTR + aq * 4) * 4;
    const uint32_t bdst0 = su + ABYTES + (ar * BSTR + aq * 4) * 4;
    const uint32_t bdst1 = su + ABYTES + ((ar + 128) * BSTR + aq * 4) * 4;

    // -- ldmatrix per-lane offsets (bytes, relative to stage base) --
    const int la = lane & 7, lb = (lane >> 3) & 1, lc = (lane >> 4) & 1;
    // A frag mt: row = wm + mt*16 + la + lb*8, col words = lc*4 (+ kk*8)
    const uint32_t aoff0 = ((wm + la + lb * 8) * ASTR + lc * 4) * 4;
    const uint32_t aoff1 = aoff0 + 16 * ASTR * 4;
    // B frag pair p: row = wn + p*16 + la + lc*8, col words = lb*4 (+ kk*8)
    uint32_t boff[4];
    #pragma unroll
    for (int p = 0; p < 4; p++)
        boff[p] = ABYTES + ((wn + p * 16 + la + lc * 8) * BSTR + lb * 4) * 4;

    // -- prologue: stages 0..2 --
    #pragma unroll
    for (int s = 0; s < NSTG - 1; ++s) {
        const uint32_t o = s * STG;
        cp16(adst + o,  asrc  + s * BK);
        cp16(bdst0 + o, bsrc0 + s * BK);
        cp16(bdst1 + o, bsrc1 + s * BK);
        cp_commit();
    }

    #pragma unroll 1
    for (int s = 0; s < NK; ++s) {
        cp_wait2();
        __syncthreads();
        if (s + 3 < NK) {
            const uint32_t o = ((s + 3) & 3) * STG;
            cp16(adst + o,  asrc  + (size_t)(s + 3) * BK);
            cp16(bdst0 + o, bsrc0 + (size_t)(s + 3) * BK);
            cp16(bdst1 + o, bsrc1 + (size_t)(s + 3) * BK);
        }
        cp_commit();

        const uint32_t sa = su + (s & 3) * STG;
        #pragma unroll
        for (int kk = 0; kk < 2; ++kk) {
            uint32_t af[2][4], bf[4][4];
            ldsm4(af[0], sa + aoff0 + kk * 32);
            ldsm4(af[1], sa + aoff1 + kk * 32);
            #pragma unroll
            for (int p = 0; p < 4; p++) ldsm4(bf[p], sa + boff[p] + kk * 32);
            #pragma unroll
            for (int mt = 0; mt < 2; mt++)
                #pragma unroll
                for (int nt = 0; nt < 8; nt++)
                    mma8(acc[mt][nt], af[mt], &bf[nt >> 1][(nt & 1) * 2]);
        }
    }
}

// ===================== GEMM1: xc @ W1t -> GLU -> g_fw =====================
__global__ __launch_bounds__(NTHR, 1) void k_gemm1(
    const float* __restrict__ b1, const float* __restrict__ rw)
{
    extern __shared__ char smraw[];
    const uint32_t su = smem_u32(smraw);
    const int m0 = blockIdx.x * BM;
    const int n0 = blockIdx.y * BN;
    const int e  = blockIdx.z;

    float acc[2][8][4];
    #pragma unroll
    for (int a = 0; a < 2; a++)
        #pragma unroll
        for (int b = 0; b < 8; b++)
            #pragma unroll
            for (int q = 0; q < 4; q++) acc[a][b][q] = 0.f;

    gemm_main(g_xc + (size_t)m0 * HID,
              g_w1t + ((size_t)e * N1 + n0) * HID,
              HID, HID / BK, su, acc);

    // epilogue: bias + clamp + GLU + rw-scale -> g_fw (tf32-rounded)
    const int lane = threadIdx.x & 31, w = threadIdx.x >> 5;
    const int wm = (w & 3) * 32, wn = (w >> 2) * 64;
    uint32_t* fw = (uint32_t*)g_fw;
    #pragma unroll
    for (int mt = 0; mt < 2; mt++) {
        const int r = m0 + wm + mt * 16 + (lane >> 2);
        const float rwa = rw[r * EXP + e];
        const float rwb = rw[(r + 8) * EXP + e];
        #pragma unroll
        for (int nt = 0; nt < 8; nt++) {
            const int cn = n0 + wn + nt * 8 + (lane & 3) * 2;  // even = gate
            const float bg = b1[e * N1 + cn];
            const float bu = b1[e * N1 + cn + 1];
            const int d = cn >> 1;
            {
                float g = fminf(acc[mt][nt][0] + bg, 7.f);
                float u = fminf(fmaxf(acc[mt][nt][1] + bu, -7.f), 7.f);
                float glu = g / (1.f + __expf(-1.702f * g));
                fw[(size_t)r * K2P + e * 2048 + d] = f2tf((u + 1.f) * glu * rwa);
            }
            {
                float g = fminf(acc[mt][nt][2] + bg, 7.f);
                float u = fminf(fmaxf(acc[mt][nt][3] + bu, -7.f), 7.f);
                float glu = g / (1.f + __expf(-1.702f * g));
                fw[(size_t)(r + 8) * K2P + e * 2048 + d] = f2tf((u + 1.f) * glu * rwb);
            }
        }
    }
}

// ===================== GEMM2: g_fw @ W2t (bias folded in K) -> out =====================
__global__ __launch_bounds__(NTHR, 1) void k_gemm2(float* __restrict__ out)
{
    extern __shared__ char smraw[];
    const uint32_t su = smem_u32(smraw);
    const int m0 = blockIdx.x * BM;
    const int n0 = blockIdx.y * BN;

    float acc[2][8][4];
    #pragma unroll
    for (int a = 0; a < 2; a++)
        #pragma unroll
        for (int b = 0; b < 8; b++)
            #pragma unroll
            for (int q = 0; q < 4; q++) acc[a][b][q] = 0.f;

    gemm_main(g_fw + (size_t)m0 * K2P,
              g_w2t + (size_t)n0 * K2P,
              K2P, K2P / BK, su, acc);  // 1026 k-steps

    const int lane = threadIdx.x & 31, w = threadIdx.x >> 5;
    const int wm = (w & 3) * 32, wn = (w >> 2) * 64;
    #pragma unroll
    for (int mt = 0; mt < 2; mt++) {
        const int r = m0 + wm + mt * 16 + (lane >> 2);
        #pragma unroll
        for (int nt = 0; nt < 8; nt++) {
            const int cn = n0 + wn + nt * 8 + (lane & 3) * 2;
            *(float2*)&out[(size_t)r * HID + cn] =
                make_float2(acc[mt][nt][0], acc[mt][nt][1]);
            *(float2*)&out[(size_t)(r + 8) * HID + cn] =
                make_float2(acc[mt][nt][2], acc[mt][nt][3]);
        }
    }
}

// ===================== prepass kernels =====================
__global__ void k_cvt(const float* __restrict__ x) {
    const size_t i = ((size_t)blockIdx.x * 256 + threadIdx.x) * 4;
    float4 v = *(const float4*)(x + i);
    *(uint4*)((uint32_t*)g_xc + i) = make_uint4(f2tf(v.x), f2tf(v.y), f2tf(v.z), f2tf(v.w));
}

// W1[e][h][n] -> g_w1t[e][n][h]  (tf32-rounded)
__global__ void k_tr1(const float* __restrict__ w1) {
    __shared__ float s[32][33];
    const int tx = threadIdx.x, ty = threadIdx.y;
    const int n0 = blockIdx.x * 32, h0 = blockIdx.y * 32, e = blockIdx.z;
    #pragma unroll
    for (int i = 0; i < 4; i++)
        s[ty + 8 * i][tx] = w1[((size_t)e * HID + h0 + ty + 8 * i) * N1 + n0 + tx];
    __syncthreads();
    #pragma unroll
    for (int i = 0; i < 4; i++)
        ((uint32_t*)g_w1t)[((size_t)e * N1 + n0 + ty + 8 * i) * HID + h0 + tx] =
            f2tf(s[tx][ty + 8 * i]);
}

// W2flat[k][h] -> g_w2t[h][k]  (tf32-rounded, stride K2P)
__global__ void k_tr2(const float* __restrict__ w2) {
    __shared__ float s[32][33];
    const int tx = threadIdx.x, ty = threadIdx.y;
    const int h0 = blockIdx.x * 32, k0 = blockIdx.y * 32;
    #pragma unroll
    for (int i = 0; i < 4; i++)
        s[ty + 8 * i][tx] = w2[(size_t)(k0 + ty + 8 * i) * HID + h0 + tx];
    __syncthreads();
    #pragma unroll
    for (int i = 0; i < 4; i++)
        ((uint32_t*)g_w2t)[(size_t)(h0 + ty + 8 * i) * K2P + k0 + tx] =
            f2tf(s[tx][ty + 8 * i]);
}

// tails: g_fw[:,16384+j] = rw[t][j] (j<8) else 0 ;  g_w2t[:,16384+j] = b2[j][h] (j<8) else 0
__global__ void k_tail(const float* __restrict__ rw, const float* __restrict__ b2) {
    const int row = blockIdx.x;        // 0..2047
    const int t = threadIdx.x;         // 0..63
    const int j = t & 31;
    if (t < 32)
        ((uint32_t*)g_fw)[(size_t)row * K2P + K2 + j] = (j < 8) ? f2tf(rw[row * EXP + j]) : 0u;
    else
        ((uint32_t*)g_w2t)[(size_t)row * K2P + K2 + j] = (j < 8) ? f2tf(b2[j * HID + row]) : 0u;
}

// ===================== launch =====================
extern "C" void kernel_launch(void* const* d_in, const int* in_sizes, int n_in,
                              void* d_out, int out_size) {
    const float* x  = (const float*)d_in[0];
    const float* rw = (const float*)d_in[1];
    const float* w1 = (const float*)d_in[2];
    const float* b1 = (const float*)d_in[3];
    const float* w2 = (const float*)d_in[4];
    const float* b2 = (const float*)d_in[5];
    float* out = (float*)d_out;

    cudaFuncSetAttribute(k_gemm1, cudaFuncAttributeMaxDynamicSharedMemorySize, SMEM_SZ);
    cudaFuncSetAttribute(k_gemm2, cudaFuncAttributeMaxDynamicSharedMemorySize, SMEM_SZ);

    k_cvt <<<(T_TOK * HID) / 1024, 256>>>(x);
    k_tr1 <<<dim3(N1 / 32, HID / 32, EXP), dim3(32, 8)>>>(w1);
    k_tr2 <<<dim3(HID / 32, K2 / 32), dim3(32, 8)>>>(w2);
    k_tail<<<2048, 64>>>(rw, b2);

    k_gemm1<<<dim3(T_TOK / BM, N1 / BN, EXP), NTHR, SMEM_SZ>>>(b1, rw);
    k_gemm2<<<dim3(T_TOK / BM, K2 == 16384 ? HID / BN : HID / BN), NTHR, SMEM_SZ>>>(out);
}

// round 7
// speedup vs baseline: 1.1699x; 1.1421x over previous
#include <cuda_runtime.h>
#include <cstdint>

// ---- problem dims ----
#define T_TOK 2048
#define HID   2048
#define EXP   8
#define N1    4096
#define K2    16384
#define K2P   16416   // K2 + 32: bias folded into K (cols 16384..16391 = rw / down_b)

// ---- tiling ----
constexpr int BM = 128, BN = 256, BK = 32;
constexpr int NTHR = 512;             // 16 warps: 4 (m) x 4 (n), warp tile 32x64
constexpr int NSTG = 3;
constexpr int ASTR = 36, BSTR = 36;   // words/row (32 data + 4 pad): conflict-free
constexpr int ABYTES = BM * ASTR * 4;       // 18432
constexpr int BBYTES = BN * BSTR * 4;       // 36864
constexpr int STG = ABYTES + BBYTES;        // 55296
constexpr int SMEM_SZ = NSTG * STG;         // 165888

// ---- scratch (device globals; allocation forbidden) ----
__device__ __align__(1024) float g_xc [(size_t)T_TOK * HID];      // tf32-rounded x
__device__ __align__(1024) float g_w1t[(size_t)EXP * N1 * HID];   // [e][n][h]
__device__ __align__(1024) float g_w2t[(size_t)HID * K2P];        // [h][k] (+bias tail)
__device__ __align__(1024) float g_fw [(size_t)T_TOK * K2P];      // rw-scaled GLU (+rw tail)

// ===================== helpers =====================
__device__ __forceinline__ uint32_t smem_u32(const void* p) {
    uint32_t a;
    asm("{ .reg .u64 t; cvta.to.shared.u64 t, %1; cvt.u32.u64 %0, t; }" : "=r"(a) : "l"(p));
    return a;
}
__device__ __forceinline__ uint32_t f2tf(float f) {
    uint32_t u; asm("cvt.rna.tf32.f32 %0, %1;" : "=r"(u) : "f"(f)); return u;
}
__device__ __forceinline__ void mma8(float* c, const uint32_t* a, const uint32_t* b) {
    asm volatile(
        "mma.sync.aligned.m16n8k8.row.col.f32.tf32.tf32.f32 "
        "{%0,%1,%2,%3}, {%4,%5,%6,%7}, {%8,%9}, {%0,%1,%2,%3};"
        : "+f"(c[0]), "+f"(c[1]), "+f"(c[2]), "+f"(c[3])
        : "r"(a[0]), "r"(a[1]), "r"(a[2]), "r"(a[3]), "r"(b[0]), "r"(b[1]));
}
__device__ __forceinline__ void ldsm4(uint32_t* r, uint32_t addr) {
    asm volatile("ldmatrix.sync.aligned.m8n8.x4.shared.b16 {%0,%1,%2,%3}, [%4];"
                 : "=r"(r[0]), "=r"(r[1]), "=r"(r[2]), "=r"(r[3]) : "r"(addr));
}
__device__ __forceinline__ void cp16(uint32_t s, const void* g) {
    asm volatile("cp.async.cg.shared.global [%0], [%1], 16;" :: "r"(s), "l"(g) : "memory");
}
__device__ __forceinline__ void cp_commit() {
    asm volatile("cp.async.commit_group;" ::: "memory");
}
__device__ __forceinline__ void cp_wait1() {
    asm volatile("cp.async.wait_group 1;" ::: "memory");
}

// ===================== main GEMM loop =====================
// pA: BM rows x lda (k-contiguous tf32). pB: BN rows x lda. acc: warp tile 32x64.
__device__ __forceinline__ void gemm_main(
    const float* __restrict__ pA, const float* __restrict__ pB,
    size_t lda, int NK, uint32_t su, float acc[2][8][4])
{
    const int tid  = threadIdx.x;
    const int lane = tid & 31;
    const int w    = tid >> 5;
    const int wm   = (w & 3) * 32;
    const int wn   = (w >> 2) * 64;

    // -- cp.async addressing: 8 threads per 128B row --
    const int rr = tid >> 3;            // 0..63 (base row, +64 per rep)
    const int q  = tid & 7;             // 16B quad in row
    const float*  asrc = pA + (size_t)rr * lda + q * 4;
    const float*  bsrc = pB + (size_t)rr * lda + q * 4;
    const uint32_t adst = su + (rr * ASTR + q * 4) * 4;
    const uint32_t bdst = su + ABYTES + (rr * BSTR + q * 4) * 4;
    const size_t gstep = (size_t)lda * 64;       // 64 rows in floats... (bytes below)

    auto load_stage = [&](int s, int st) {
        const uint32_t o = st * STG;
        const size_t ko = (size_t)s * BK;
        #pragma unroll
        for (int i = 0; i < 2; i++)                       // A: 128 rows
            cp16(adst + o + i * 64 * ASTR * 4, asrc + ko + i * gstep);
        #pragma unroll
        for (int i = 0; i < 4; i++)                       // B: 256 rows
            cp16(bdst + o + i * 64 * BSTR * 4, bsrc + ko + i * gstep);
        cp_commit();
    };

    // -- ldmatrix per-lane offsets (bytes, rel. to stage base) --
    const int la = lane & 7, lb = (lane >> 3) & 1, lc = (lane >> 4) & 1;
    const uint32_t aoff0 = ((wm + la + lb * 8) * ASTR + lc * 4) * 4;
    const uint32_t aoff1 = aoff0 + 16 * ASTR * 4;
    uint32_t boff[4];
    #pragma unroll
    for (int p = 0; p < 4; p++)
        boff[p] = ABYTES + ((wn + p * 16 + la + lc * 8) * BSTR + lb * 4) * 4;

    // -- prologue: stages 0,1 --
    load_stage(0, 0);
    load_stage(1, 1);

    int st = 0;
    #pragma unroll 1
    for (int s = 0; s < NK; ++s) {
        cp_wait1();
        __syncthreads();
        if (s + 2 < NK) {
            int nst = st + 2; if (nst >= NSTG) nst -= NSTG;
            load_stage(s + 2, nst);
        } else {
            cp_commit();   // keep group accounting uniform
        }

        const uint32_t sa = su + st * STG;
        #pragma unroll
        for (int kk = 0; kk < 4; ++kk) {
            uint32_t af[2][4], bf[4][4];
            ldsm4(af[0], sa + aoff0 + kk * 32);
            ldsm4(af[1], sa + aoff1 + kk * 32);
            #pragma unroll
            for (int p = 0; p < 4; p++) ldsm4(bf[p], sa + boff[p] + kk * 32);
            #pragma unroll
            for (int mt = 0; mt < 2; mt++)
                #pragma unroll
                for (int nt = 0; nt < 8; nt++)
                    mma8(acc[mt][nt], af[mt], &bf[nt >> 1][(nt & 1) * 2]);
        }
        if (++st >= NSTG) st -= NSTG;
        __syncthreads();
    }
}

// ===================== GEMM1: xc @ W1t -> GLU -> g_fw =====================
__global__ __launch_bounds__(NTHR, 1) void k_gemm1(
    const float* __restrict__ b1, const float* __restrict__ rw)
{
    extern __shared__ char smraw[];
    const uint32_t su = smem_u32(smraw);
    const int m0 = blockIdx.x * BM;
    const int n0 = blockIdx.y * BN;
    const int e  = blockIdx.z;

    float acc[2][8][4];
    #pragma unroll
    for (int a = 0; a < 2; a++)
        #pragma unroll
        for (int b = 0; b < 8; b++)
            #pragma unroll
            for (int q = 0; q < 4; q++) acc[a][b][q] = 0.f;

    gemm_main(g_xc + (size_t)m0 * HID,
              g_w1t + ((size_t)e * N1 + n0) * HID,
              HID, HID / BK, su, acc);

    const int lane = threadIdx.x & 31, w = threadIdx.x >> 5;
    const int wm = (w & 3) * 32, wn = (w >> 2) * 64;
    uint32_t* fw = (uint32_t*)g_fw;
    #pragma unroll
    for (int mt = 0; mt < 2; mt++) {
        const int r = m0 + wm + mt * 16 + (lane >> 2);
        const float rwa = rw[r * EXP + e];
        const float rwb = rw[(r + 8) * EXP + e];
        #pragma unroll
        for (int nt = 0; nt < 8; nt++) {
            const int cn = n0 + wn + nt * 8 + (lane & 3) * 2;  // even = gate
            const float bg = b1[e * N1 + cn];
            const float bu = b1[e * N1 + cn + 1];
            const int d = cn >> 1;
            {
                float g = fminf(acc[mt][nt][0] + bg, 7.f);
                float u = fminf(fmaxf(acc[mt][nt][1] + bu, -7.f), 7.f);
                float glu = g / (1.f + __expf(-1.702f * g));
                fw[(size_t)r * K2P + e * 2048 + d] = f2tf((u + 1.f) * glu * rwa);
            }
            {
                float g = fminf(acc[mt][nt][2] + bg, 7.f);
                float u = fminf(fmaxf(acc[mt][nt][3] + bu, -7.f), 7.f);
                float glu = g / (1.f + __expf(-1.702f * g));
                fw[(size_t)(r + 8) * K2P + e * 2048 + d] = f2tf((u + 1.f) * glu * rwb);
            }
        }
    }
}

// ===================== GEMM2: g_fw @ W2t (bias in K-tail) -> out =====================
__global__ __launch_bounds__(NTHR, 1) void k_gemm2(float* __restrict__ out)
{
    extern __shared__ char smraw[];
    const uint32_t su = smem_u32(smraw);
    const int m0 = blockIdx.x * BM;
    const int n0 = blockIdx.y * BN;

    float acc[2][8][4];
    #pragma unroll
    for (int a = 0; a < 2; a++)
        #pragma unroll
        for (int b = 0; b < 8; b++)
            #pragma unroll
            for (int q = 0; q < 4; q++) acc[a][b][q] = 0.f;

    gemm_main(g_fw + (size_t)m0 * K2P,
              g_w2t + (size_t)n0 * K2P,
              K2P, K2P / BK, su, acc);     // 513 k-steps

    const int lane = threadIdx.x & 31, w = threadIdx.x >> 5;
    const int wm = (w & 3) * 32, wn = (w >> 2) * 64;
    #pragma unroll
    for (int mt = 0; mt < 2; mt++) {
        const int r = m0 + wm + mt * 16 + (lane >> 2);
        #pragma unroll
        for (int nt = 0; nt < 8; nt++) {
            const int cn = n0 + wn + nt * 8 + (lane & 3) * 2;
            *(float2*)&out[(size_t)r * HID + cn] =
                make_float2(acc[mt][nt][0], acc[mt][nt][1]);
            *(float2*)&out[(size_t)(r + 8) * HID + cn] =
                make_float2(acc[mt][nt][2], acc[mt][nt][3]);
        }
    }
}

// ===================== prepass =====================
// W1[e][h][n] -> g_w1t[e][n][h]  (tf32-rounded)
__global__ void k_tr1(const float* __restrict__ w1) {
    __shared__ float s[32][33];
    const int tx = threadIdx.x, ty = threadIdx.y;
    const int n0 = blockIdx.x * 32, h0 = blockIdx.y * 32, e = blockIdx.z;
    #pragma unroll
    for (int i = 0; i < 4; i++)
        s[ty + 8 * i][tx] = w1[((size_t)e * HID + h0 + ty + 8 * i) * N1 + n0 + tx];
    __syncthreads();
    #pragma unroll
    for (int i = 0; i < 4; i++)
        ((uint32_t*)g_w1t)[((size_t)e * N1 + n0 + ty + 8 * i) * HID + h0 + tx] =
            f2tf(s[tx][ty + 8 * i]);
}

// W2flat[k][h] -> g_w2t[h][k]  (tf32-rounded, stride K2P)
__global__ void k_tr2(const float* __restrict__ w2) {
    __shared__ float s[32][33];
    const int tx = threadIdx.x, ty = threadIdx.y;
    const int h0 = blockIdx.x * 32, k0 = blockIdx.y * 32;
    #pragma unroll
    for (int i = 0; i < 4; i++)
        s[ty + 8 * i][tx] = w2[(size_t)(k0 + ty + 8 * i) * HID + h0 + tx];
    __syncthreads();
    #pragma unroll
    for (int i = 0; i < 4; i++)
        ((uint32_t*)g_w2t)[(size_t)(h0 + ty + 8 * i) * K2P + k0 + tx] =
            f2tf(s[tx][ty + 8 * i]);
}

// fused: x -> tf32 g_xc  AND  K-tail init for g_fw / g_w2t
__global__ void k_misc(const float* __restrict__ x, const float* __restrict__ rw,
                       const float* __restrict__ b2) {
    const int b = blockIdx.x;
    if (b < 2048) {
        // cvt: block handles 2048 floats
        const size_t base = (size_t)b * 2048 + threadIdx.x * 8;
        #pragma unroll
        for (int i = 0; i < 2; i++) {
            float4 v = *(const float4*)(x + base + i * 4);
            *(uint4*)((uint32_t*)g_xc + base + i * 4) =
                make_uint4(f2tf(v.x), f2tf(v.y), f2tf(v.z), f2tf(v.w));
        }
    } else {
        const int row = b - 2048;          // 0..2047
        const int t = threadIdx.x;
        if (t < 32)
            ((uint32_t*)g_fw)[(size_t)row * K2P + K2 + t] =
                (t < 8) ? f2tf(rw[row * EXP + t]) : 0u;
        else if (t < 64) {
            const int j = t - 32;
            ((uint32_t*)g_w2t)[(size_t)row * K2P + K2 + j] =
                (j < 8) ? f2tf(b2[j * HID + row]) : 0u;
        }
    }
}

// ===================== launch =====================
extern "C" void kernel_launch(void* const* d_in, const int* in_sizes, int n_in,
                              void* d_out, int out_size) {
    const float* x  = (const float*)d_in[0];
    const float* rw = (const float*)d_in[1];
    const float* w1 = (const float*)d_in[2];
    const float* b1 = (const float*)d_in[3];
    const float* w2 = (const float*)d_in[4];
    const float* b2 = (const float*)d_in[5];
    float* out = (float*)d_out;

    cudaFuncSetAttribute(k_gemm1, cudaFuncAttributeMaxDynamicSharedMemorySize, SMEM_SZ);
    cudaFuncSetAttribute(k_gemm2, cudaFuncAttributeMaxDynamicSharedMemorySize, SMEM_SZ);

    k_tr1 <<<dim3(N1 / 32, HID / 32, EXP), dim3(32, 8)>>>(w1);
    k_tr2 <<<dim3(HID / 32, K2 / 32), dim3(32, 8)>>>(w2);
    k_misc<<<4096, 256>>>(x, rw, b2);

    k_gemm1<<<dim3(T_TOK / BM, N1 / BN, EXP), NTHR, SMEM_SZ>>>(b1, rw);
    k_gemm2<<<dim3(T_TOK / BM, HID / BN), NTHR, SMEM_SZ>>>(out);
}